// round 6
// baseline (speedup 1.0000x reference)
#include <cuda_runtime.h>
#include <cuda_fp16.h>
#include <math.h>
#include <stdint.h>

#define MP 120000
#define GTC 938     // ceil(MP / 128)
#define GTC2 469    // ceil(MP / 256)

// ---------------- scratch (static device globals; no runtime allocs) ----------
__device__ float  g_V[MP * 64];
__device__ __half g_H16[MP * 64];
__device__ __half g_B16[MP * 64];
__device__ __half g_W1a16[4 * 4096];
__device__ __half g_W1b16[4 * 4096];
__device__ __half g_W316[4 * 27 * 4096];
__device__ __half g_Wp16[4 * 4096];
__device__ __half g_Wa16[4 * 4096];
__device__ float  g_ms[4 * MP * 64];
__device__ float  g_vsum4[4 * MP * 64];
__device__ float  g_vcnt4[4 * MP];

__device__ __forceinline__ float lrelu(float x, float a) { return x > 0.f ? x : a * x; }

__device__ __forceinline__ uint32_t smem_u32(const void* p) {
    uint32_t a;
    asm("{ .reg .u64 t; cvta.to.shared.u64 t, %1; cvt.u32.u64 %0, t; }" : "=r"(a) : "l"(p));
    return a;
}

__device__ __forceinline__ void ldm4(uint32_t r[4], uint32_t addr) {
    asm volatile("ldmatrix.sync.aligned.m8n8.x4.shared.b16 {%0,%1,%2,%3}, [%4];"
                 : "=r"(r[0]), "=r"(r[1]), "=r"(r[2]), "=r"(r[3]) : "r"(addr));
}

__device__ __forceinline__ void mma16816(float c[4], const uint32_t a[4],
                                         uint32_t b0, uint32_t b1) {
    asm volatile(
        "mma.sync.aligned.m16n8k16.row.col.f32.f16.f16.f32 "
        "{%0,%1,%2,%3},{%4,%5,%6,%7},{%8,%9},{%0,%1,%2,%3};"
        : "+f"(c[0]), "+f"(c[1]), "+f"(c[2]), "+f"(c[3])
        : "r"(a[0]), "r"(a[1]), "r"(a[2]), "r"(a[3]), "r"(b0), "r"(b1));
}

#define CP16(dst, src) \
    asm volatile("cp.async.cg.shared.global [%0], [%1], 16;" :: "r"(dst), "l"(src))
#define CP_COMMIT() asm volatile("cp.async.commit_group;" ::: "memory")
#define CP_WAIT(n)  asm volatile("cp.async.wait_group %0;" :: "n"(n) : "memory")
#define STS_ZERO(dst) do { uint32_t _z = 0; \
    asm volatile("st.shared.v4.b32 [%0], {%1,%1,%1,%1};" :: "r"(dst), "r"(_z)); } while (0)

// ========== MMA core (M-tile 128): A(128x64) x W(64x64)^T, 8 warps ============
__device__ __forceinline__ void mma_tile_64(uint32_t a_s, uint32_t w_s,
                                            int lane, int wm, int wn,
                                            float acc[2][4][4]) {
#pragma unroll
    for (int kb = 0; kb < 4; kb++) {
        uint32_t a[2][4], wh[2][4];
#pragma unroll
        for (int mt = 0; mt < 2; mt++) {
            int r = wm + mt * 16 + (lane & 15);
            int lc = kb * 2 + (lane >> 4);
            ldm4(a[mt], a_s + r * 128 + ((lc ^ (r & 7)) << 4));
        }
#pragma unroll
        for (int np = 0; np < 2; np++) {
            int r = wn + np * 16 + (lane & 7) + ((lane & 16) ? 8 : 0);
            int lc = kb * 2 + ((lane >> 3) & 1);
            ldm4(wh[np], w_s + r * 128 + ((lc ^ (r & 7)) << 4));
        }
#pragma unroll
        for (int mt = 0; mt < 2; mt++)
#pragma unroll
            for (int nt = 0; nt < 4; nt++) {
                int np = nt >> 1, q = (nt & 1) * 2;
                mma16816(acc[mt][nt], a[mt], wh[np][q], wh[np][q + 1]);
            }
    }
}

// ========== MMA core (M-tile 256): warp tile 64x32, 8 warps ===================
__device__ __forceinline__ void mma_tile_256(uint32_t a_s, uint32_t w_s,
                                             int lane, int wm, int wn,
                                             float acc[4][4][4]) {
#pragma unroll
    for (int kb = 0; kb < 4; kb++) {
        uint32_t a[4][4], wh[2][4];
#pragma unroll
        for (int mt = 0; mt < 4; mt++) {
            int r = wm + mt * 16 + (lane & 15);
            int lc = kb * 2 + (lane >> 4);
            ldm4(a[mt], a_s + r * 128 + ((lc ^ (r & 7)) << 4));
        }
#pragma unroll
        for (int np = 0; np < 2; np++) {
            int r = wn + np * 16 + (lane & 7) + ((lane & 16) ? 8 : 0);
            int lc = kb * 2 + ((lane >> 3) & 1);
            ldm4(wh[np], w_s + r * 128 + ((lc ^ (r & 7)) << 4));
        }
#pragma unroll
        for (int mt = 0; mt < 4; mt++)
#pragma unroll
            for (int nt = 0; nt < 4; nt++) {
                int np = nt >> 1, q = (nt & 1) * 2;
                mma16816(acc[mt][nt], a[mt], wh[np][q], wh[np][q + 1]);
            }
    }
}

// =================== weight prep: transpose + fp16 ===========================
__global__ void wprep_kernel(const float* __restrict__ w1a, const float* __restrict__ w1b,
                             const float* __restrict__ w3, const float* __restrict__ wp,
                             const float* __restrict__ wa,
                             __half* __restrict__ o1a, __half* __restrict__ o1b,
                             __half* __restrict__ o3, __half* __restrict__ op,
                             __half* __restrict__ oa) {
    int g = blockIdx.x * 256 + threadIdx.x;
    if (g >= 124 * 4096) return;
    int t = g >> 12;
    int rc = g & 4095;
    int d = rc >> 6, c = rc & 63;
    if (t < 4)
        o1a[(size_t)t * 4096 + d * 64 + c] = __float2half_rn(w1a[(size_t)t * 4096 + c * 64 + d]);
    else if (t < 8)
        o1b[(size_t)(t - 4) * 4096 + d * 64 + c] = __float2half_rn(w1b[(size_t)(t - 4) * 4096 + c * 64 + d]);
    else if (t < 116)
        o3[(size_t)(t - 8) * 4096 + d * 64 + c] = __float2half_rn(w3[(size_t)(t - 8) * 4096 + c * 64 + d]);
    else if (t < 120)
        op[(size_t)(t - 116) * 4096 + d * 64 + c] = __float2half_rn(wp[(size_t)(t - 116) * 4096 + c * 64 + d]);
    else
        oa[(size_t)(t - 120) * 4096 + d * 64 + c] = __float2half_rn(wa[(size_t)(t - 120) * 4096 + c * 64 + d]);
}

// ============= first-layer GEMM: fp32 input, fp16 out  =======================
__global__ __launch_bounds__(256) void gemm64hf_kernel(
    const float* __restrict__ Xf, const __half* __restrict__ W,
    const float* __restrict__ s, const float* __restrict__ b,
    __half* __restrict__ outh) {
    __shared__ __align__(16) char smA[16384];
    __shared__ __align__(16) char smW[8192];
    const uint32_t a_s = smem_u32(smA);
    const uint32_t w_s = smem_u32(smW);
    const int tid = threadIdx.x;
    const int lane = tid & 31, wid = tid >> 5;
    const int m0 = blockIdx.x * 128;

#pragma unroll
    for (int j = 0; j < 2; j++) {
        int f = tid + j * 256;
        int r = f >> 3, c = f & 7;
        CP16(w_s + r * 128 + ((c ^ (r & 7)) << 4), W + (size_t)r * 64 + c * 8);
    }
    CP_COMMIT();
#pragma unroll
    for (int j = 0; j < 4; j++) {
        int f = tid + j * 256;
        int r = f >> 3, c = f & 7;
        uint32_t dst = a_s + r * 128 + ((c ^ (r & 7)) << 4);
        int m = m0 + r;
        if (m < MP) {
            float4 v0 = *(const float4*)&Xf[(size_t)m * 64 + c * 8];
            float4 v1 = *(const float4*)&Xf[(size_t)m * 64 + c * 8 + 4];
            __half2 h0 = __float22half2_rn(make_float2(v0.x, v0.y));
            __half2 h1 = __float22half2_rn(make_float2(v0.z, v0.w));
            __half2 h2 = __float22half2_rn(make_float2(v1.x, v1.y));
            __half2 h3 = __float22half2_rn(make_float2(v1.z, v1.w));
            uint32_t q0 = *(uint32_t*)&h0, q1 = *(uint32_t*)&h1;
            uint32_t q2 = *(uint32_t*)&h2, q3 = *(uint32_t*)&h3;
            asm volatile("st.shared.v4.b32 [%0], {%1,%2,%3,%4};"
                         :: "r"(dst), "r"(q0), "r"(q1), "r"(q2), "r"(q3));
        } else {
            STS_ZERO(dst);
        }
    }
    CP_WAIT(0);
    __syncthreads();

    const int wm = (wid >> 1) * 32;
    const int wn = (wid & 1) * 32;
    float acc[2][4][4] = {};
    mma_tile_64(a_s, w_s, lane, wm, wn, acc);

    const int qr = lane >> 2, qc = lane & 3;
#pragma unroll
    for (int mt = 0; mt < 2; mt++)
#pragma unroll
        for (int nt = 0; nt < 4; nt++) {
            int col = wn + nt * 8 + qc * 2;
            float2 s2 = *(const float2*)&s[col];
            float2 b2 = *(const float2*)&b[col];
            int r0 = m0 + wm + mt * 16 + qr;
            int r1 = r0 + 8;
            if (r0 < MP) *(__half2*)&outh[(size_t)r0 * 64 + col] = __float22half2_rn(
                make_float2(lrelu(acc[mt][nt][0] * s2.x + b2.x, 0.01f),
                            lrelu(acc[mt][nt][1] * s2.y + b2.y, 0.01f)));
            if (r1 < MP) *(__half2*)&outh[(size_t)r1 * 64 + col] = __float22half2_rn(
                make_float2(lrelu(acc[mt][nt][2] * s2.x + b2.x, 0.01f),
                            lrelu(acc[mt][nt][3] * s2.y + b2.y, 0.01f)));
        }
}

// ====== fused double GEMM: (X@W1)*s1+b1 -> lrelu -> @W2*s2+b2 -> lrelu ========
__global__ __launch_bounds__(256) void gemm64h2_kernel(
    const __half* __restrict__ X,
    const __half* __restrict__ W1, const float* __restrict__ s1, const float* __restrict__ b1,
    const __half* __restrict__ W2, const float* __restrict__ s2, const float* __restrict__ b2,
    __half* __restrict__ outh) {
    __shared__ __align__(16) char smA[16384];
    __shared__ __align__(16) char smB[16384];
    __shared__ __align__(16) char smW1[8192];
    __shared__ __align__(16) char smW2[8192];
    const uint32_t a_s = smem_u32(smA);
    const uint32_t b_s = smem_u32(smB);
    const uint32_t w1_s = smem_u32(smW1);
    const uint32_t w2_s = smem_u32(smW2);
    const int tid = threadIdx.x;
    const int lane = tid & 31, wid = tid >> 5;
    const int m0 = blockIdx.x * 128;

#pragma unroll
    for (int j = 0; j < 4; j++) {
        int f = tid + j * 256;
        int r = f >> 3, c = f & 7;
        uint32_t dst = a_s + r * 128 + ((c ^ (r & 7)) << 4);
        if (m0 + r < MP) CP16(dst, X + (size_t)(m0 + r) * 64 + c * 8);
        else STS_ZERO(dst);
    }
#pragma unroll
    for (int j = 0; j < 2; j++) {
        int f = tid + j * 256;
        int r = f >> 3, c = f & 7;
        CP16(w1_s + r * 128 + ((c ^ (r & 7)) << 4), W1 + (size_t)r * 64 + c * 8);
        CP16(w2_s + r * 128 + ((c ^ (r & 7)) << 4), W2 + (size_t)r * 64 + c * 8);
    }
    CP_COMMIT();
    CP_WAIT(0);
    __syncthreads();

    const int wm = (wid >> 1) * 32;
    const int wn = (wid & 1) * 32;
    const int qr = lane >> 2, qc = lane & 3;

    float acc[2][4][4] = {};
    mma_tile_64(a_s, w1_s, lane, wm, wn, acc);

    // epilogue 1 -> smB (fp16, swizzled)
#pragma unroll
    for (int mt = 0; mt < 2; mt++)
#pragma unroll
        for (int nt = 0; nt < 4; nt++) {
            int col = wn + nt * 8 + qc * 2;
            float2 sv = *(const float2*)&s1[col];
            float2 bv = *(const float2*)&b1[col];
            int lr0 = wm + mt * 16 + qr;
            int lr1 = lr0 + 8;
            __half2 h0 = __float22half2_rn(
                make_float2(lrelu(acc[mt][nt][0] * sv.x + bv.x, 0.01f),
                            lrelu(acc[mt][nt][1] * sv.y + bv.y, 0.01f)));
            __half2 h1 = __float22half2_rn(
                make_float2(lrelu(acc[mt][nt][2] * sv.x + bv.x, 0.01f),
                            lrelu(acc[mt][nt][3] * sv.y + bv.y, 0.01f)));
            uint32_t d0 = b_s + lr0 * 128 + (((col >> 3) ^ (lr0 & 7)) << 4) + ((col * 2) & 15);
            uint32_t d1 = b_s + lr1 * 128 + (((col >> 3) ^ (lr1 & 7)) << 4) + ((col * 2) & 15);
            *(__half2*)(smB + (d0 - b_s)) = h0;
            *(__half2*)(smB + (d1 - b_s)) = h1;
        }
    __syncthreads();

    float acc2[2][4][4] = {};
    mma_tile_64(b_s, w2_s, lane, wm, wn, acc2);

#pragma unroll
    for (int mt = 0; mt < 2; mt++)
#pragma unroll
        for (int nt = 0; nt < 4; nt++) {
            int col = wn + nt * 8 + qc * 2;
            float2 sv = *(const float2*)&s2[col];
            float2 bv = *(const float2*)&b2[col];
            int r0 = m0 + wm + mt * 16 + qr;
            int r1 = r0 + 8;
            if (r0 < MP) *(__half2*)&outh[(size_t)r0 * 64 + col] = __float22half2_rn(
                make_float2(lrelu(acc2[mt][nt][0] * sv.x + bv.x, 0.01f),
                            lrelu(acc2[mt][nt][1] * sv.y + bv.y, 0.01f)));
            if (r1 < MP) *(__half2*)&outh[(size_t)r1 * 64 + col] = __float22half2_rn(
                make_float2(lrelu(acc2[mt][nt][2] * sv.x + bv.x, 0.01f),
                            lrelu(acc2[mt][nt][3] * sv.y + bv.y, 0.01f)));
        }
}

// ============ final 1x1: fp16 in, fp32 out with residual ======================
__global__ __launch_bounds__(256) void gemm64h_res_kernel(
    const __half* __restrict__ X, const __half* __restrict__ W,
    const float* __restrict__ s, const float* __restrict__ b,
    float* __restrict__ outf, const float* __restrict__ feats) {
    __shared__ __align__(16) char smA[16384];
    __shared__ __align__(16) char smW[8192];
    const uint32_t a_s = smem_u32(smA);
    const uint32_t w_s = smem_u32(smW);
    const int tid = threadIdx.x;
    const int lane = tid & 31, wid = tid >> 5;
    const int m0 = blockIdx.x * 128;

#pragma unroll
    for (int j = 0; j < 4; j++) {
        int f = tid + j * 256;
        int r = f >> 3, c = f & 7;
        uint32_t dst = a_s + r * 128 + ((c ^ (r & 7)) << 4);
        if (m0 + r < MP) CP16(dst, X + (size_t)(m0 + r) * 64 + c * 8);
        else STS_ZERO(dst);
    }
#pragma unroll
    for (int j = 0; j < 2; j++) {
        int f = tid + j * 256;
        int r = f >> 3, c = f & 7;
        CP16(w_s + r * 128 + ((c ^ (r & 7)) << 4), W + (size_t)r * 64 + c * 8);
    }
    CP_COMMIT();
    CP_WAIT(0);
    __syncthreads();

    const int wm = (wid >> 1) * 32;
    const int wn = (wid & 1) * 32;
    float acc[2][4][4] = {};
    mma_tile_64(a_s, w_s, lane, wm, wn, acc);

    const int qr = lane >> 2, qc = lane & 3;
#pragma unroll
    for (int mt = 0; mt < 2; mt++)
#pragma unroll
        for (int nt = 0; nt < 4; nt++) {
            int col = wn + nt * 8 + qc * 2;
            float2 sv = *(const float2*)&s[col];
            float2 bv = *(const float2*)&b[col];
            int r0 = m0 + wm + mt * 16 + qr;
            int r1 = r0 + 8;
            if (r0 < MP) {
                float2 fr = *(const float2*)&feats[(size_t)r0 * 64 + col];
                *(float2*)&outf[(size_t)r0 * 64 + col] = make_float2(
                    lrelu(lrelu(acc[mt][nt][0] * sv.x + bv.x, 0.01f) + fr.x, 0.1f),
                    lrelu(lrelu(acc[mt][nt][1] * sv.y + bv.y, 0.01f) + fr.y, 0.1f));
            }
            if (r1 < MP) {
                float2 fr = *(const float2*)&feats[(size_t)r1 * 64 + col];
                *(float2*)&outf[(size_t)r1 * 64 + col] = make_float2(
                    lrelu(lrelu(acc[mt][nt][2] * sv.x + bv.x, 0.01f) + fr.x, 0.1f),
                    lrelu(lrelu(acc[mt][nt][3] * sv.y + bv.y, 0.01f) + fr.y, 0.1f));
            }
        }
}

// ====== conv 27-tap, M-tile 256, warp tile 64x32, 3-stage pipeline ============
// smem: nidx[27][256] (27648) | A 32KB x3 | W 8KB x3 = 150528 bytes
#define CT_NIDX 0
#define CT_A(st) (27648 + (st) * 32768)
#define CT_W(st) (125952 + (st) * 8192)
#define CT_TOT   150528

__device__ __forceinline__ void ct_fill(uint32_t sb, int stage, int k,
                                        const int* __restrict__ nidxT,
                                        const __half* __restrict__ H,
                                        const __half* __restrict__ Wh, int tid) {
    uint32_t a_s = sb + CT_A(stage);
    uint32_t h_s = sb + CT_W(stage);
#pragma unroll
    for (int j = 0; j < 8; j++) {
        int t = tid + j * 256;
        int r = t >> 3, c = t & 7;
        int row = nidxT[k * 256 + r];
        uint32_t dst = a_s + r * 128 + ((c ^ (r & 7)) << 4);
        if (row >= 0) CP16(dst, H + (size_t)row * 64 + c * 8);
        else STS_ZERO(dst);
    }
    const __half* WhK = Wh + (size_t)k * 4096;
#pragma unroll
    for (int j = 0; j < 2; j++) {
        int t = tid + j * 256;
        int r = t >> 3, c = t & 7;
        CP16(h_s + r * 128 + ((c ^ (r & 7)) << 4), WhK + r * 64 + c * 8);
    }
}

__global__ __launch_bounds__(256, 1) void conv27_mma_kernel(
    const __half* __restrict__ H, const int* __restrict__ nbr,
    const __half* __restrict__ Wh,
    const float* __restrict__ s, const float* __restrict__ b,
    __half* __restrict__ out) {
    extern __shared__ char smc[];
    const uint32_t sb = smem_u32(smc);
    const int tid = threadIdx.x;
    const int lane = tid & 31, wid = tid >> 5;
    const int m0 = blockIdx.x * 256;
    int* nidxT = (int*)smc;
    for (int t = tid; t < 27 * 256; t += 256) {
        int k = t >> 8, r = t & 255;
        int m = m0 + r;
        nidxT[t] = (m < MP) ? nbr[(size_t)m * 27 + k] : -1;
    }
    __syncthreads();

    ct_fill(sb, 0, 0, nidxT, H, Wh, tid);
    CP_COMMIT();
    ct_fill(sb, 1, 1, nidxT, H, Wh, tid);
    CP_COMMIT();

    const int wm = (wid >> 1) * 64;
    const int wn = (wid & 1) * 32;
    float acc[4][4][4] = {};
    int stage = 0;

    for (int k = 0; k < 27; k++) {
        if (k < 26) CP_WAIT(1);
        else        CP_WAIT(0);
        __syncthreads();
        if (k < 25) {
            int ns = stage + 2;
            if (ns >= 3) ns -= 3;
            ct_fill(sb, ns, k + 2, nidxT, H, Wh, tid);
            CP_COMMIT();
        }
        mma_tile_256(sb + CT_A(stage), sb + CT_W(stage), lane, wm, wn, acc);
        if (++stage == 3) stage = 0;
    }

    const int qr = lane >> 2, qc = lane & 3;
#pragma unroll
    for (int mt = 0; mt < 4; mt++)
#pragma unroll
        for (int nt = 0; nt < 4; nt++) {
            int col = wn + nt * 8 + qc * 2;
            float2 s2 = *(const float2*)&s[col];
            float2 b2 = *(const float2*)&b[col];
            int r0 = m0 + wm + mt * 16 + qr;
            int r1 = r0 + 8;
            if (r0 < MP) *(__half2*)&out[(size_t)r0 * 64 + col] = __float22half2_rn(
                make_float2(lrelu(acc[mt][nt][0] * s2.x + b2.x, 0.01f),
                            lrelu(acc[mt][nt][1] * s2.y + b2.y, 0.01f)));
            if (r1 < MP) *(__half2*)&out[(size_t)r1 * 64 + col] = __float22half2_rn(
                make_float2(lrelu(acc[mt][nt][2] * s2.x + b2.x, 0.01f),
                            lrelu(acc[mt][nt][3] * s2.y + b2.y, 0.01f)));
        }
}

// =================== batched scatter-mean over all 4 scales ===================
__global__ void zero_all_kernel(float* __restrict__ vsum4, float* __restrict__ vcnt4) {
    int gid = blockIdx.x * 256 + threadIdx.x;
    if (gid < 4 * MP * 16) ((float4*)vsum4)[gid] = make_float4(0.f, 0.f, 0.f, 0.f);
    if (gid < 4 * MP) vcnt4[gid] = 0.f;
}

__global__ void scatter_all_kernel(const float* __restrict__ V, const int* __restrict__ inv,
                                   float* __restrict__ vsum4, float* __restrict__ vcnt4) {
    int gid = blockIdx.x * 256 + threadIdx.x;
    if (gid >= 4 * MP * 64) return;
    int si = gid / (MP * 64);
    int rem = gid - si * (MP * 64);
    int m = rem >> 6, c = rem & 63;
    int sg = inv[si * MP + m];
    atomicAdd(&vsum4[(size_t)si * MP * 64 + sg * 64 + c], V[rem]);
    if (c == 0) atomicAdd(&vcnt4[si * MP + sg], 1.0f);
}

// ============ tensorized proj: Os=(V-mean)*V (fp16) @ proj_w, grid (GTC,4) ====
__global__ __launch_bounds__(256) void proj_mma_kernel(
    const float* __restrict__ V, const int* __restrict__ inv,
    const float* __restrict__ vsum4, const float* __restrict__ vcnt4,
    const __half* __restrict__ Wp, const float* __restrict__ pb,
    const float* __restrict__ ps, const float* __restrict__ pbb,
    float* __restrict__ ms) {
    __shared__ __align__(16) char smA[16384];
    __shared__ __align__(16) char smW[8192];
    const uint32_t a_s = smem_u32(smA);
    const uint32_t w_s = smem_u32(smW);
    const int tid = threadIdx.x;
    const int lane = tid & 31, wid = tid >> 5;
    const int m0 = blockIdx.x * 128;
    const int si = blockIdx.y;
    const int* seg = inv + (size_t)si * MP;
    const float* vsum = vsum4 + (size_t)si * MP * 64;
    const float* vcnt = vcnt4 + (size_t)si * MP;
    float* msO = ms + (size_t)si * MP * 64;

#pragma unroll
    for (int j = 0; j < 2; j++) {
        int f = tid + j * 256;
        int r = f >> 3, c = f & 7;
        CP16(w_s + r * 128 + ((c ^ (r & 7)) << 4),
             Wp + (size_t)si * 4096 + r * 64 + c * 8);
    }
    CP_COMMIT();
#pragma unroll
    for (int j = 0; j < 4; j++) {
        int f = tid + j * 256;
        int r = f >> 3, c = f & 7;
        uint32_t dst = a_s + r * 128 + ((c ^ (r & 7)) << 4);
        int m = m0 + r;
        if (m < MP) {
            int sg = seg[m];
            float rc = 1.0f / fmaxf(vcnt[sg], 1.0f);
            float4 v0 = *(const float4*)&V[(size_t)m * 64 + c * 8];
            float4 v1 = *(const float4*)&V[(size_t)m * 64 + c * 8 + 4];
            float4 u0 = *(const float4*)&vsum[(size_t)sg * 64 + c * 8];
            float4 u1 = *(const float4*)&vsum[(size_t)sg * 64 + c * 8 + 4];
            __half2 h0 = __float22half2_rn(make_float2((v0.x - u0.x * rc) * v0.x,
                                                       (v0.y - u0.y * rc) * v0.y));
            __half2 h1 = __float22half2_rn(make_float2((v0.z - u0.z * rc) * v0.z,
                                                       (v0.w - u0.w * rc) * v0.w));
            __half2 h2 = __float22half2_rn(make_float2((v1.x - u1.x * rc) * v1.x,
                                                       (v1.y - u1.y * rc) * v1.y));
            __half2 h3 = __float22half2_rn(make_float2((v1.z - u1.z * rc) * v1.z,
                                                       (v1.w - u1.w * rc) * v1.w));
            uint32_t q0 = *(uint32_t*)&h0, q1 = *(uint32_t*)&h1;
            uint32_t q2 = *(uint32_t*)&h2, q3 = *(uint32_t*)&h3;
            asm volatile("st.shared.v4.b32 [%0], {%1,%2,%3,%4};"
                         :: "r"(dst), "r"(q0), "r"(q1), "r"(q2), "r"(q3));
        } else {
            STS_ZERO(dst);
        }
    }
    CP_WAIT(0);
    __syncthreads();

    const int wm = (wid >> 1) * 32;
    const int wn = (wid & 1) * 32;
    float acc[2][4][4] = {};
    mma_tile_64(a_s, w_s, lane, wm, wn, acc);

    const int qr = lane >> 2, qc = lane & 3;
#pragma unroll
    for (int mt = 0; mt < 2; mt++)
#pragma unroll
        for (int nt = 0; nt < 4; nt++) {
            int col = wn + nt * 8 + qc * 2;
            float2 bv = *(const float2*)&pb[si * 64 + col];
            float2 sv = *(const float2*)&ps[si * 64 + col];
            float2 b2 = *(const float2*)&pbb[si * 64 + col];
            int r0 = m0 + wm + mt * 16 + qr;
            int r1 = r0 + 8;
            if (r0 < MP) *(float2*)&msO[(size_t)r0 * 64 + col] = make_float2(
                lrelu((acc[mt][nt][0] + bv.x) * sv.x + b2.x, 0.01f),
                lrelu((acc[mt][nt][1] + bv.y) * sv.y + b2.y, 0.01f));
            if (r1 < MP) *(float2*)&msO[(size_t)r1 * 64 + col] = make_float2(
                lrelu((acc[mt][nt][2] + bv.x) * sv.x + b2.x, 0.01f),
                lrelu((acc[mt][nt][3] + bv.y) * sv.y + b2.y, 0.01f));
        }
}

// ===== tensorized attn: sumx built in-kernel (fp16), 4 GEMMs, fused output ====
__global__ __launch_bounds__(256) void attn_mma_kernel(
    const float* __restrict__ ms, const __half* __restrict__ Wa,
    const float* __restrict__ ab, const float* __restrict__ as_,
    const float* __restrict__ abb, float* __restrict__ fused) {
    __shared__ __align__(16) char smA[16384];
    __shared__ __align__(16) char smW[8192];
    const uint32_t a_s = smem_u32(smA);
    const uint32_t w_s = smem_u32(smW);
    const int tid = threadIdx.x;
    const int lane = tid & 31, wid = tid >> 5;
    const int m0 = blockIdx.x * 128;

#pragma unroll
    for (int j = 0; j < 4; j++) {
        int f = tid + j * 256;
        int r = f >> 3, c = f & 7;
        uint32_t dst = a_s + r * 128 + ((c ^ (r & 7)) << 4);
        int m = m0 + r;
        if (m < MP) {
            float sx[8] = {};
#pragma unroll
            for (int i = 0; i < 4; i++) {
                float4 v0 = *(const float4*)&ms[((size_t)i * MP + m) * 64 + c * 8];
                float4 v1 = *(const float4*)&ms[((size_t)i * MP + m) * 64 + c * 8 + 4];
                sx[0] += v0.x; sx[1] += v0.y; sx[2] += v0.z; sx[3] += v0.w;
                sx[4] += v1.x; sx[5] += v1.y; sx[6] += v1.z; sx[7] += v1.w;
            }
            __half2 h0 = __float22half2_rn(make_float2(sx[0], sx[1]));
            __half2 h1 = __float22half2_rn(make_float2(sx[2], sx[3]));
            __half2 h2 = __float22half2_rn(make_float2(sx[4], sx[5]));
            __half2 h3 = __float22half2_rn(make_float2(sx[6], sx[7]));
            uint32_t q0 = *(uint32_t*)&h0, q1 = *(uint32_t*)&h1;
            uint32_t q2 = *(uint32_t*)&h2, q3 = *(uint32_t*)&h3;
            asm volatile("st.shared.v4.b32 [%0], {%1,%2,%3,%4};"
                         :: "r"(dst), "r"(q0), "r"(q1), "r"(q2), "r"(q3));
        } else {
            STS_ZERO(dst);
        }
    }

    const int wm = (wid >> 1) * 32;
    const int wn = (wid & 1) * 32;
    const int qr = lane >> 2, qc = lane & 3;
    float fac[2][4][4] = {};

    for (int i = 0; i < 4; i++) {
        __syncthreads();
#pragma unroll
        for (int j = 0; j < 2; j++) {
            int f = tid + j * 256;
            int r = f >> 3, c = f & 7;
            CP16(w_s + r * 128 + ((c ^ (r & 7)) << 4),
                 Wa + (size_t)i * 4096 + r * 64 + c * 8);
        }
        CP_COMMIT();
        CP_WAIT(0);
        __syncthreads();

        float acc[2][4][4] = {};
        mma_tile_64(a_s, w_s, lane, wm, wn, acc);

#pragma unroll
        for (int mt = 0; mt < 2; mt++)
#pragma unroll
            for (int nt = 0; nt < 4; nt++) {
                int col = wn + nt * 8 + qc * 2;
                float2 bv = *(const float2*)&ab[i * 64 + col];
                float2 sv = *(const float2*)&as_[i * 64 + col];
                float2 b2 = *(const float2*)&abb[i * 64 + col];
                int r0 = m0 + wm + mt * 16 + qr;
                int r1 = r0 + 8;
                if (r0 < MP) {
                    float2 mv = *(const float2*)&ms[((size_t)i * MP + r0) * 64 + col];
                    float a0 = 1.0f / (1.0f + __expf(-((acc[mt][nt][0] + bv.x) * sv.x + b2.x)));
                    float a1 = 1.0f / (1.0f + __expf(-((acc[mt][nt][1] + bv.y) * sv.y + b2.y)));
                    fac[mt][nt][0] += a0 * mv.x;
                    fac[mt][nt][1] += a1 * mv.y;
                }
                if (r1 < MP) {
                    float2 mv = *(const float2*)&ms[((size_t)i * MP + r1) * 64 + col];
                    float a2 = 1.0f / (1.0f + __expf(-((acc[mt][nt][2] + bv.x) * sv.x + b2.x)));
                    float a3 = 1.0f / (1.0f + __expf(-((acc[mt][nt][3] + bv.y) * sv.y + b2.y)));
                    fac[mt][nt][2] += a2 * mv.x;
                    fac[mt][nt][3] += a3 * mv.y;
                }
            }
    }

#pragma unroll
    for (int mt = 0; mt < 2; mt++)
#pragma unroll
        for (int nt = 0; nt < 4; nt++) {
            int col = wn + nt * 8 + qc * 2;
            int r0 = m0 + wm + mt * 16 + qr;
            int r1 = r0 + 8;
            if (r0 < MP) *(float2*)&fused[(size_t)r0 * 64 + col] =
                make_float2(fac[mt][nt][0], fac[mt][nt][1]);
            if (r1 < MP) *(float2*)&fused[(size_t)r1 * 64 + col] =
                make_float2(fac[mt][nt][2], fac[mt][nt][3]);
        }
}

// ================================ N=20 heads ==================================
__global__ __launch_bounds__(256) void gemm_n20_kernel(
    const float* __restrict__ X, const float* __restrict__ W,
    const float* __restrict__ b, float* __restrict__ out) {
    __shared__ float Xs[128 * 68];
    __shared__ float Ws[64 * 20];
    __shared__ float bs[20];
    const int tid = threadIdx.x;
    const int m0 = blockIdx.x * 128;
#pragma unroll
    for (int j = 0; j < 8; j++) {
        int f = tid + 256 * j;
        int r = f >> 4, c4 = f & 15;
        int m = m0 + r;
        float4 v = make_float4(0.f, 0.f, 0.f, 0.f);
        if (m < MP) v = *(const float4*)&X[(size_t)m * 64 + c4 * 4];
        *(float4*)&Xs[r * 68 + c4 * 4] = v;
    }
    for (int f = tid; f < 64 * 20; f += 256) Ws[f] = W[f];
    if (tid < 20) bs[tid] = b[tid];
    __syncthreads();
    int r = tid >> 1, half = tid & 1, n0 = half * 10;
    int m = m0 + r;
    if (m < MP) {
        float acc[10];
#pragma unroll
        for (int j = 0; j < 10; j++) acc[j] = bs[n0 + j];
#pragma unroll 8
        for (int c = 0; c < 64; c++) {
            float x = Xs[r * 68 + c];
#pragma unroll
            for (int j = 0; j < 10; j++) acc[j] += x * Ws[c * 20 + n0 + j];
        }
#pragma unroll
        for (int j = 0; j < 10; j++) out[(size_t)m * 20 + n0 + j] = acc[j];
    }
}

// ==============================================================================
extern "C" void kernel_launch(void* const* d_in, const int* in_sizes, int n_in,
                              void* d_out, int out_size) {
    const float* feats   = (const float*)d_in[0];
    const float* w1a     = (const float*)d_in[1];
    const float* s1a     = (const float*)d_in[2];
    const float* b1a     = (const float*)d_in[3];
    const float* w3      = (const float*)d_in[4];
    const float* s3      = (const float*)d_in[5];
    const float* b3      = (const float*)d_in[6];
    const float* w1b     = (const float*)d_in[7];
    const float* s1b     = (const float*)d_in[8];
    const float* b1b     = (const float*)d_in[9];
    const float* aux_w   = (const float*)d_in[10];
    const float* aux_b   = (const float*)d_in[11];
    const float* proj_w  = (const float*)d_in[12];
    const float* proj_b  = (const float*)d_in[13];
    const float* proj_s  = (const float*)d_in[14];
    const float* proj_bb = (const float*)d_in[15];
    const float* attn_w  = (const float*)d_in[16];
    const float* attn_b  = (const float*)d_in[17];
    const float* attn_s  = (const float*)d_in[18];
    const float* attn_bb = (const float*)d_in[19];
    const float* head_w  = (const float*)d_in[20];
    const float* head_b  = (const float*)d_in[21];
    const int*   nbr     = (const int*)d_in[22];
    const int*   inv     = (const int*)d_in[23];

    float* out    = (float*)d_out;
    float* fused  = out;
    float* logits = out + (size_t)MP * 64;
    float* aux    = out + (size_t)MP * 84;

    float *pV, *pms, *pvs, *pvc;
    __half *pH16, *pB16, *pW1a, *pW1b, *pW3, *pWp, *pWa;
    cudaGetSymbolAddress((void**)&pV, g_V);
    cudaGetSymbolAddress((void**)&pms, g_ms);
    cudaGetSymbolAddress((void**)&pvs, g_vsum4);
    cudaGetSymbolAddress((void**)&pvc, g_vcnt4);
    cudaGetSymbolAddress((void**)&pH16, g_H16);
    cudaGetSymbolAddress((void**)&pB16, g_B16);
    cudaGetSymbolAddress((void**)&pW1a, g_W1a16);
    cudaGetSymbolAddress((void**)&pW1b, g_W1b16);
    cudaGetSymbolAddress((void**)&pW3, g_W316);
    cudaGetSymbolAddress((void**)&pWp, g_Wp16);
    cudaGetSymbolAddress((void**)&pWa, g_Wa16);

    cudaFuncSetAttribute(conv27_mma_kernel, cudaFuncAttributeMaxDynamicSharedMemorySize, CT_TOT);

    wprep_kernel<<<(124 * 4096 + 255) / 256, 256>>>(w1a, w1b, w3, proj_w, attn_w,
                                                    pW1a, pW1b, pW3, pWp, pWa);

    gemm64hf_kernel<<<GTC, 256>>>(feats, pW1a, s1a, b1a, pH16);
    for (int i = 0; i < 4; i++) {
        conv27_mma_kernel<<<GTC2, 256, CT_TOT>>>(pH16, nbr, pW3 + (size_t)i * 27 * 4096,
                                                 s3 + i * 64, b3 + i * 64, pB16);
        if (i < 3) {
            gemm64h2_kernel<<<GTC, 256>>>(pB16,
                                          pW1b + (size_t)i * 4096, s1b + i * 64, b1b + i * 64,
                                          pW1a + (size_t)(i + 1) * 4096, s1a + (i + 1) * 64,
                                          b1a + (i + 1) * 64, pH16);
        } else {
            gemm64h_res_kernel<<<GTC, 256>>>(pB16, pW1b + (size_t)i * 4096, s1b + i * 64,
                                             b1b + i * 64, pV, feats);
        }
    }

    gemm_n20_kernel<<<938, 256>>>(pV, aux_w, aux_b, aux);

    zero_all_kernel<<<30000, 256>>>(pvs, pvc);
    scatter_all_kernel<<<120000, 256>>>(pV, inv, pvs, pvc);
    {
        dim3 grid(GTC, 4);
        proj_mma_kernel<<<grid, 256>>>(pV, inv, pvs, pvc, pWp,
                                       proj_b, proj_s, proj_bb, pms);
    }
    attn_mma_kernel<<<GTC, 256>>>(pms, pWa, attn_b, attn_s, attn_bb, fused);
    gemm_n20_kernel<<<938, 256>>>(fused, head_w, head_b, logits);
}

// round 7
// speedup vs baseline: 1.1334x; 1.1334x over previous
#include <cuda_runtime.h>
#include <cuda_fp16.h>
#include <math.h>
#include <stdint.h>

#define MP 120000
#define GTC 938     // ceil(MP / 128)

// ---------------- scratch (static device globals; no runtime allocs) ----------
__device__ float  g_V[MP * 64];
__device__ __half g_H16[MP * 64];
__device__ __half g_B16[MP * 64];
__device__ __half g_W1a16[4 * 4096];
__device__ __half g_W1b16[4 * 4096];
__device__ __half g_Wp16[4 * 4096];
__device__ __half g_Wa16[4 * 4096];
__device__ uint4  g_Wf[4 * 27 * 512];   // conv W in mma-fragment order
__device__ float  g_ms[4 * MP * 64];
__device__ float  g_vsum4[4 * MP * 64];
__device__ float  g_vcnt4[4 * MP];

__device__ __forceinline__ float lrelu(float x, float a) { return x > 0.f ? x : a * x; }

__device__ __forceinline__ uint32_t smem_u32(const void* p) {
    uint32_t a;
    asm("{ .reg .u64 t; cvta.to.shared.u64 t, %1; cvt.u32.u64 %0, t; }" : "=r"(a) : "l"(p));
    return a;
}

__device__ __forceinline__ void ldm4(uint32_t r[4], uint32_t addr) {
    asm volatile("ldmatrix.sync.aligned.m8n8.x4.shared.b16 {%0,%1,%2,%3}, [%4];"
                 : "=r"(r[0]), "=r"(r[1]), "=r"(r[2]), "=r"(r[3]) : "r"(addr));
}

__device__ __forceinline__ void mma16816(float c[4], const uint32_t a[4],
                                         uint32_t b0, uint32_t b1) {
    asm volatile(
        "mma.sync.aligned.m16n8k16.row.col.f32.f16.f16.f32 "
        "{%0,%1,%2,%3},{%4,%5,%6,%7},{%8,%9},{%0,%1,%2,%3};"
        : "+f"(c[0]), "+f"(c[1]), "+f"(c[2]), "+f"(c[3])
        : "r"(a[0]), "r"(a[1]), "r"(a[2]), "r"(a[3]), "r"(b0), "r"(b1));
}

#define CP16(dst, src) \
    asm volatile("cp.async.cg.shared.global [%0], [%1], 16;" :: "r"(dst), "l"(src))
#define CP_COMMIT() asm volatile("cp.async.commit_group;" ::: "memory")
#define CP_WAIT(n)  asm volatile("cp.async.wait_group %0;" :: "n"(n) : "memory")
#define STS_ZERO(dst) do { uint32_t _z = 0; \
    asm volatile("st.shared.v4.b32 [%0], {%1,%1,%1,%1};" :: "r"(dst), "r"(_z)); } while (0)

// ========== MMA core (M-tile 128): A(128x64) x W(64x64)^T, 8 warps ============
__device__ __forceinline__ void mma_tile_64(uint32_t a_s, uint32_t w_s,
                                            int lane, int wm, int wn,
                                            float acc[2][4][4]) {
#pragma unroll
    for (int kb = 0; kb < 4; kb++) {
        uint32_t a[2][4], wh[2][4];
#pragma unroll
        for (int mt = 0; mt < 2; mt++) {
            int r = wm + mt * 16 + (lane & 15);
            int lc = kb * 2 + (lane >> 4);
            ldm4(a[mt], a_s + r * 128 + ((lc ^ (r & 7)) << 4));
        }
#pragma unroll
        for (int np = 0; np < 2; np++) {
            int r = wn + np * 16 + (lane & 7) + ((lane & 16) ? 8 : 0);
            int lc = kb * 2 + ((lane >> 3) & 1);
            ldm4(wh[np], w_s + r * 128 + ((lc ^ (r & 7)) << 4));
        }
#pragma unroll
        for (int mt = 0; mt < 2; mt++)
#pragma unroll
            for (int nt = 0; nt < 4; nt++) {
                int np = nt >> 1, q = (nt & 1) * 2;
                mma16816(acc[mt][nt], a[mt], wh[np][q], wh[np][q + 1]);
            }
    }
}

// =================== weight prep: transpose + fp16 (1x1/proj/attn) ============
__global__ void wprep_kernel(const float* __restrict__ w1a, const float* __restrict__ w1b,
                             const float* __restrict__ wp, const float* __restrict__ wa,
                             __half* __restrict__ o1a, __half* __restrict__ o1b,
                             __half* __restrict__ op, __half* __restrict__ oa) {
    int g = blockIdx.x * 256 + threadIdx.x;
    if (g >= 16 * 4096) return;
    int t = g >> 12;
    int rc = g & 4095;
    int d = rc >> 6, c = rc & 63;
    if (t < 4)
        o1a[(size_t)t * 4096 + d * 64 + c] = __float2half_rn(w1a[(size_t)t * 4096 + c * 64 + d]);
    else if (t < 8)
        o1b[(size_t)(t - 4) * 4096 + d * 64 + c] = __float2half_rn(w1b[(size_t)(t - 4) * 4096 + c * 64 + d]);
    else if (t < 12)
        op[(size_t)(t - 8) * 4096 + d * 64 + c] = __float2half_rn(wp[(size_t)(t - 8) * 4096 + c * 64 + d]);
    else
        oa[(size_t)(t - 12) * 4096 + d * 64 + c] = __float2half_rn(wa[(size_t)(t - 12) * 4096 + c * 64 + d]);
}

// ===== conv W -> mma-fragment order: Wf[lt][wn][kb][p][lane] = uint4 ==========
// For m16n8k16 B-fragment: lane l holds n = base_n + (l>>2),
// b0 halves k = kb*16 + (l&3)*2 (+1), b1 halves k = +8.
__global__ void wfrag_kernel(const float* __restrict__ w3, uint4* __restrict__ Wf) {
    int idx = blockIdx.x * 256 + threadIdx.x;
    if (idx >= 4 * 27 * 512) return;
    int lane = idx & 31;
    int p    = (idx >> 5) & 1;
    int kb   = (idx >> 6) & 3;
    int wn   = (idx >> 8) & 1;
    int lt   = idx >> 9;
    int g = lane >> 2, t = lane & 3;
    const float* W = w3 + (size_t)lt * 4096;   // [c][d]
    uint32_t r[4];
#pragma unroll
    for (int j = 0; j < 4; j++) {
        int nt = 2 * p + (j >> 1);
        int breg = j & 1;
        int n = wn * 32 + nt * 8 + g;
        int cb = kb * 16 + breg * 8 + 2 * t;
        unsigned short h0 = __half_as_ushort(__float2half_rn(W[cb * 64 + n]));
        unsigned short h1 = __half_as_ushort(__float2half_rn(W[(cb + 1) * 64 + n]));
        r[j] = (uint32_t)h0 | ((uint32_t)h1 << 16);
    }
    Wf[idx] = make_uint4(r[0], r[1], r[2], r[3]);
}

// ============= first-layer GEMM: fp32 input, fp16 out  =======================
__global__ __launch_bounds__(256) void gemm64hf_kernel(
    const float* __restrict__ Xf, const __half* __restrict__ W,
    const float* __restrict__ s, const float* __restrict__ b,
    __half* __restrict__ outh) {
    __shared__ __align__(16) char smA[16384];
    __shared__ __align__(16) char smW[8192];
    const uint32_t a_s = smem_u32(smA);
    const uint32_t w_s = smem_u32(smW);
    const int tid = threadIdx.x;
    const int lane = tid & 31, wid = tid >> 5;
    const int m0 = blockIdx.x * 128;

#pragma unroll
    for (int j = 0; j < 2; j++) {
        int f = tid + j * 256;
        int r = f >> 3, c = f & 7;
        CP16(w_s + r * 128 + ((c ^ (r & 7)) << 4), W + (size_t)r * 64 + c * 8);
    }
    CP_COMMIT();
#pragma unroll
    for (int j = 0; j < 4; j++) {
        int f = tid + j * 256;
        int r = f >> 3, c = f & 7;
        uint32_t dst = a_s + r * 128 + ((c ^ (r & 7)) << 4);
        int m = m0 + r;
        if (m < MP) {
            float4 v0 = *(const float4*)&Xf[(size_t)m * 64 + c * 8];
            float4 v1 = *(const float4*)&Xf[(size_t)m * 64 + c * 8 + 4];
            __half2 h0 = __float22half2_rn(make_float2(v0.x, v0.y));
            __half2 h1 = __float22half2_rn(make_float2(v0.z, v0.w));
            __half2 h2 = __float22half2_rn(make_float2(v1.x, v1.y));
            __half2 h3 = __float22half2_rn(make_float2(v1.z, v1.w));
            uint32_t q0 = *(uint32_t*)&h0, q1 = *(uint32_t*)&h1;
            uint32_t q2 = *(uint32_t*)&h2, q3 = *(uint32_t*)&h3;
            asm volatile("st.shared.v4.b32 [%0], {%1,%2,%3,%4};"
                         :: "r"(dst), "r"(q0), "r"(q1), "r"(q2), "r"(q3));
        } else {
            STS_ZERO(dst);
        }
    }
    CP_WAIT(0);
    __syncthreads();

    const int wm = (wid >> 1) * 32;
    const int wn = (wid & 1) * 32;
    float acc[2][4][4] = {};
    mma_tile_64(a_s, w_s, lane, wm, wn, acc);

    const int qr = lane >> 2, qc = lane & 3;
#pragma unroll
    for (int mt = 0; mt < 2; mt++)
#pragma unroll
        for (int nt = 0; nt < 4; nt++) {
            int col = wn + nt * 8 + qc * 2;
            float2 s2 = *(const float2*)&s[col];
            float2 b2 = *(const float2*)&b[col];
            int r0 = m0 + wm + mt * 16 + qr;
            int r1 = r0 + 8;
            if (r0 < MP) *(__half2*)&outh[(size_t)r0 * 64 + col] = __float22half2_rn(
                make_float2(lrelu(acc[mt][nt][0] * s2.x + b2.x, 0.01f),
                            lrelu(acc[mt][nt][1] * s2.y + b2.y, 0.01f)));
            if (r1 < MP) *(__half2*)&outh[(size_t)r1 * 64 + col] = __float22half2_rn(
                make_float2(lrelu(acc[mt][nt][2] * s2.x + b2.x, 0.01f),
                            lrelu(acc[mt][nt][3] * s2.y + b2.y, 0.01f)));
        }
}

// ====== fused double GEMM: (X@W1)*s1+b1 -> lrelu -> @W2*s2+b2 -> lrelu ========
__global__ __launch_bounds__(256) void gemm64h2_kernel(
    const __half* __restrict__ X,
    const __half* __restrict__ W1, const float* __restrict__ s1, const float* __restrict__ b1,
    const __half* __restrict__ W2, const float* __restrict__ s2, const float* __restrict__ b2,
    __half* __restrict__ outh) {
    __shared__ __align__(16) char smA[16384];
    __shared__ __align__(16) char smB[16384];
    __shared__ __align__(16) char smW1[8192];
    __shared__ __align__(16) char smW2[8192];
    const uint32_t a_s = smem_u32(smA);
    const uint32_t b_s = smem_u32(smB);
    const uint32_t w1_s = smem_u32(smW1);
    const uint32_t w2_s = smem_u32(smW2);
    const int tid = threadIdx.x;
    const int lane = tid & 31, wid = tid >> 5;
    const int m0 = blockIdx.x * 128;

#pragma unroll
    for (int j = 0; j < 4; j++) {
        int f = tid + j * 256;
        int r = f >> 3, c = f & 7;
        uint32_t dst = a_s + r * 128 + ((c ^ (r & 7)) << 4);
        if (m0 + r < MP) CP16(dst, X + (size_t)(m0 + r) * 64 + c * 8);
        else STS_ZERO(dst);
    }
#pragma unroll
    for (int j = 0; j < 2; j++) {
        int f = tid + j * 256;
        int r = f >> 3, c = f & 7;
        CP16(w1_s + r * 128 + ((c ^ (r & 7)) << 4), W1 + (size_t)r * 64 + c * 8);
        CP16(w2_s + r * 128 + ((c ^ (r & 7)) << 4), W2 + (size_t)r * 64 + c * 8);
    }
    CP_COMMIT();
    CP_WAIT(0);
    __syncthreads();

    const int wm = (wid >> 1) * 32;
    const int wn = (wid & 1) * 32;
    const int qr = lane >> 2, qc = lane & 3;

    float acc[2][4][4] = {};
    mma_tile_64(a_s, w1_s, lane, wm, wn, acc);

#pragma unroll
    for (int mt = 0; mt < 2; mt++)
#pragma unroll
        for (int nt = 0; nt < 4; nt++) {
            int col = wn + nt * 8 + qc * 2;
            float2 sv = *(const float2*)&s1[col];
            float2 bv = *(const float2*)&b1[col];
            int lr0 = wm + mt * 16 + qr;
            int lr1 = lr0 + 8;
            __half2 h0 = __float22half2_rn(
                make_float2(lrelu(acc[mt][nt][0] * sv.x + bv.x, 0.01f),
                            lrelu(acc[mt][nt][1] * sv.y + bv.y, 0.01f)));
            __half2 h1 = __float22half2_rn(
                make_float2(lrelu(acc[mt][nt][2] * sv.x + bv.x, 0.01f),
                            lrelu(acc[mt][nt][3] * sv.y + bv.y, 0.01f)));
            uint32_t d0 = lr0 * 128 + (((col >> 3) ^ (lr0 & 7)) << 4) + ((col * 2) & 15);
            uint32_t d1 = lr1 * 128 + (((col >> 3) ^ (lr1 & 7)) << 4) + ((col * 2) & 15);
            *(__half2*)(smB + d0) = h0;
            *(__half2*)(smB + d1) = h1;
        }
    __syncthreads();

    float acc2[2][4][4] = {};
    mma_tile_64(b_s, w2_s, lane, wm, wn, acc2);

#pragma unroll
    for (int mt = 0; mt < 2; mt++)
#pragma unroll
        for (int nt = 0; nt < 4; nt++) {
            int col = wn + nt * 8 + qc * 2;
            float2 sv = *(const float2*)&s2[col];
            float2 bv = *(const float2*)&b2[col];
            int r0 = m0 + wm + mt * 16 + qr;
            int r1 = r0 + 8;
            if (r0 < MP) *(__half2*)&outh[(size_t)r0 * 64 + col] = __float22half2_rn(
                make_float2(lrelu(acc2[mt][nt][0] * sv.x + bv.x, 0.01f),
                            lrelu(acc2[mt][nt][1] * sv.y + bv.y, 0.01f)));
            if (r1 < MP) *(__half2*)&outh[(size_t)r1 * 64 + col] = __float22half2_rn(
                make_float2(lrelu(acc2[mt][nt][2] * sv.x + bv.x, 0.01f),
                            lrelu(acc2[mt][nt][3] * sv.y + bv.y, 0.01f)));
        }
}

// ============ final 1x1: fp16 in, fp32 out with residual ======================
__global__ __launch_bounds__(256) void gemm64h_res_kernel(
    const __half* __restrict__ X, const __half* __restrict__ W,
    const float* __restrict__ s, const float* __restrict__ b,
    float* __restrict__ outf, const float* __restrict__ feats) {
    __shared__ __align__(16) char smA[16384];
    __shared__ __align__(16) char smW[8192];
    const uint32_t a_s = smem_u32(smA);
    const uint32_t w_s = smem_u32(smW);
    const int tid = threadIdx.x;
    const int lane = tid & 31, wid = tid >> 5;
    const int m0 = blockIdx.x * 128;

#pragma unroll
    for (int j = 0; j < 4; j++) {
        int f = tid + j * 256;
        int r = f >> 3, c = f & 7;
        uint32_t dst = a_s + r * 128 + ((c ^ (r & 7)) << 4);
        if (m0 + r < MP) CP16(dst, X + (size_t)(m0 + r) * 64 + c * 8);
        else STS_ZERO(dst);
    }
#pragma unroll
    for (int j = 0; j < 2; j++) {
        int f = tid + j * 256;
        int r = f >> 3, c = f & 7;
        CP16(w_s + r * 128 + ((c ^ (r & 7)) << 4), W + (size_t)r * 64 + c * 8);
    }
    CP_COMMIT();
    CP_WAIT(0);
    __syncthreads();

    const int wm = (wid >> 1) * 32;
    const int wn = (wid & 1) * 32;
    float acc[2][4][4] = {};
    mma_tile_64(a_s, w_s, lane, wm, wn, acc);

    const int qr = lane >> 2, qc = lane & 3;
#pragma unroll
    for (int mt = 0; mt < 2; mt++)
#pragma unroll
        for (int nt = 0; nt < 4; nt++) {
            int col = wn + nt * 8 + qc * 2;
            float2 sv = *(const float2*)&s[col];
            float2 bv = *(const float2*)&b[col];
            int r0 = m0 + wm + mt * 16 + qr;
            int r1 = r0 + 8;
            if (r0 < MP) {
                float2 fr = *(const float2*)&feats[(size_t)r0 * 64 + col];
                *(float2*)&outf[(size_t)r0 * 64 + col] = make_float2(
                    lrelu(lrelu(acc[mt][nt][0] * sv.x + bv.x, 0.01f) + fr.x, 0.1f),
                    lrelu(lrelu(acc[mt][nt][1] * sv.y + bv.y, 0.01f) + fr.y, 0.1f));
            }
            if (r1 < MP) {
                float2 fr = *(const float2*)&feats[(size_t)r1 * 64 + col];
                *(float2*)&outf[(size_t)r1 * 64 + col] = make_float2(
                    lrelu(lrelu(acc[mt][nt][2] * sv.x + bv.x, 0.01f) + fr.x, 0.1f),
                    lrelu(lrelu(acc[mt][nt][3] * sv.y + bv.y, 0.01f) + fr.y, 0.1f));
            }
        }
}

// ====== conv 27-tap, M-tile 128, 2 CTA/SM, W from fragment-ordered global =====
// smem: nidxT[27][128] int (13824 -> 14336) | A stages 16KB x3 = 63488 bytes
#define CV_A(st) (14336 + (st) * 16384)
#define CV_TOT   63488

__device__ __forceinline__ void cv_fillA(uint32_t sb, int stage, int k,
                                         const int* __restrict__ nidxT,
                                         const __half* __restrict__ H, int tid) {
    uint32_t a_s = sb + CV_A(stage);
#pragma unroll
    for (int j = 0; j < 4; j++) {
        int t = tid + j * 256;
        int r = t >> 3, c = t & 7;
        int row = nidxT[k * 128 + r];
        uint32_t dst = a_s + r * 128 + ((c ^ (r & 7)) << 4);
        if (row >= 0) CP16(dst, H + (size_t)row * 64 + c * 8);
        else STS_ZERO(dst);
    }
}

__global__ __launch_bounds__(256, 2) void conv27_mma_kernel(
    const __half* __restrict__ H, const int* __restrict__ nbr,
    const uint4* __restrict__ Wf,
    const float* __restrict__ s, const float* __restrict__ b,
    __half* __restrict__ out) {
    extern __shared__ char smc[];
    const uint32_t sb = smem_u32(smc);
    const int tid = threadIdx.x;
    const int lane = tid & 31, wid = tid >> 5;
    const int m0 = blockIdx.x * 128;
    int* nidxT = (int*)smc;
    for (int t = tid; t < 27 * 128; t += 256) {
        int k = t >> 7, r = t & 127;
        int m = m0 + r;
        nidxT[t] = (m < MP) ? nbr[(size_t)m * 27 + k] : -1;
    }
    __syncthreads();

    cv_fillA(sb, 0, 0, nidxT, H, tid);
    CP_COMMIT();
    cv_fillA(sb, 1, 1, nidxT, H, tid);
    CP_COMMIT();

    const int wm = (wid >> 1) * 32;
    const int wnIdx = wid & 1;
    float acc[2][4][4] = {};
    int stage = 0;

    for (int k = 0; k < 27; k++) {
        // W fragments for this tap: 8x LDG.128 (L1-hit for 3 of 4 warps / 2nd CTA)
        const uint4* wfp = Wf + ((size_t)k * 2 + wnIdx) * 256 + lane;
        uint4 wf[8];
#pragma unroll
        for (int q = 0; q < 8; q++) wf[q] = wfp[q * 32];

        if (k < 26) CP_WAIT(1);
        else        CP_WAIT(0);
        __syncthreads();
        if (k < 25) {
            int ns = stage + 2;
            if (ns >= 3) ns -= 3;
            cv_fillA(sb, ns, k + 2, nidxT, H, tid);
            CP_COMMIT();
        }
        uint32_t a_s = sb + CV_A(stage);
#pragma unroll
        for (int kb = 0; kb < 4; kb++) {
            uint32_t a[2][4];
#pragma unroll
            for (int mt = 0; mt < 2; mt++) {
                int r = wm + mt * 16 + (lane & 15);
                int lc = kb * 2 + (lane >> 4);
                ldm4(a[mt], a_s + r * 128 + ((lc ^ (r & 7)) << 4));
            }
#pragma unroll
            for (int mt = 0; mt < 2; mt++)
#pragma unroll
                for (int nt = 0; nt < 4; nt++) {
                    uint4 W4 = wf[kb * 2 + (nt >> 1)];
                    uint32_t b0 = (nt & 1) ? W4.z : W4.x;
                    uint32_t b1 = (nt & 1) ? W4.w : W4.y;
                    mma16816(acc[mt][nt], a[mt], b0, b1);
                }
        }
        if (++stage == 3) stage = 0;
    }

    const int qr = lane >> 2, qc = lane & 3;
    const int wn = wnIdx * 32;
#pragma unroll
    for (int mt = 0; mt < 2; mt++)
#pragma unroll
        for (int nt = 0; nt < 4; nt++) {
            int col = wn + nt * 8 + qc * 2;
            float2 s2 = *(const float2*)&s[col];
            float2 b2 = *(const float2*)&b[col];
            int r0 = m0 + wm + mt * 16 + qr;
            int r1 = r0 + 8;
            if (r0 < MP) *(__half2*)&out[(size_t)r0 * 64 + col] = __float22half2_rn(
                make_float2(lrelu(acc[mt][nt][0] * s2.x + b2.x, 0.01f),
                            lrelu(acc[mt][nt][1] * s2.y + b2.y, 0.01f)));
            if (r1 < MP) *(__half2*)&out[(size_t)r1 * 64 + col] = __float22half2_rn(
                make_float2(lrelu(acc[mt][nt][2] * s2.x + b2.x, 0.01f),
                            lrelu(acc[mt][nt][3] * s2.y + b2.y, 0.01f)));
        }
}

// =================== batched scatter-mean over all 4 scales ===================
__global__ void zero_all_kernel(float* __restrict__ vsum4, float* __restrict__ vcnt4) {
    int gid = blockIdx.x * 256 + threadIdx.x;
    if (gid < 4 * MP * 16) ((float4*)vsum4)[gid] = make_float4(0.f, 0.f, 0.f, 0.f);
    if (gid < 4 * MP) vcnt4[gid] = 0.f;
}

__global__ void scatter_all_kernel(const float* __restrict__ V, const int* __restrict__ inv,
                                   float* __restrict__ vsum4, float* __restrict__ vcnt4) {
    int gid = blockIdx.x * 256 + threadIdx.x;
    if (gid >= 4 * MP * 64) return;
    int si = gid / (MP * 64);
    int rem = gid - si * (MP * 64);
    int m = rem >> 6, c = rem & 63;
    int sg = inv[si * MP + m];
    atomicAdd(&vsum4[(size_t)si * MP * 64 + sg * 64 + c], V[rem]);
    if (c == 0) atomicAdd(&vcnt4[si * MP + sg], 1.0f);
}

// ============ tensorized proj: Os=(V-mean)*V (fp16) @ proj_w, grid (GTC,4) ====
__global__ __launch_bounds__(256) void proj_mma_kernel(
    const float* __restrict__ V, const int* __restrict__ inv,
    const float* __restrict__ vsum4, const float* __restrict__ vcnt4,
    const __half* __restrict__ Wp, const float* __restrict__ pb,
    const float* __restrict__ ps, const float* __restrict__ pbb,
    float* __restrict__ ms) {
    __shared__ __align__(16) char smA[16384];
    __shared__ __align__(16) char smW[8192];
    const uint32_t a_s = smem_u32(smA);
    const uint32_t w_s = smem_u32(smW);
    const int tid = threadIdx.x;
    const int lane = tid & 31, wid = tid >> 5;
    const int m0 = blockIdx.x * 128;
    const int si = blockIdx.y;
    const int* seg = inv + (size_t)si * MP;
    const float* vsum = vsum4 + (size_t)si * MP * 64;
    const float* vcnt = vcnt4 + (size_t)si * MP;
    float* msO = ms + (size_t)si * MP * 64;

#pragma unroll
    for (int j = 0; j < 2; j++) {
        int f = tid + j * 256;
        int r = f >> 3, c = f & 7;
        CP16(w_s + r * 128 + ((c ^ (r & 7)) << 4),
             Wp + (size_t)si * 4096 + r * 64 + c * 8);
    }
    CP_COMMIT();
#pragma unroll
    for (int j = 0; j < 4; j++) {
        int f = tid + j * 256;
        int r = f >> 3, c = f & 7;
        uint32_t dst = a_s + r * 128 + ((c ^ (r & 7)) << 4);
        int m = m0 + r;
        if (m < MP) {
            int sg = seg[m];
            float rc = 1.0f / fmaxf(vcnt[sg], 1.0f);
            float4 v0 = *(const float4*)&V[(size_t)m * 64 + c * 8];
            float4 v1 = *(const float4*)&V[(size_t)m * 64 + c * 8 + 4];
            float4 u0 = *(const float4*)&vsum[(size_t)sg * 64 + c * 8];
            float4 u1 = *(const float4*)&vsum[(size_t)sg * 64 + c * 8 + 4];
            __half2 h0 = __float22half2_rn(make_float2((v0.x - u0.x * rc) * v0.x,
                                                       (v0.y - u0.y * rc) * v0.y));
            __half2 h1 = __float22half2_rn(make_float2((v0.z - u0.z * rc) * v0.z,
                                                       (v0.w - u0.w * rc) * v0.w));
            __half2 h2 = __float22half2_rn(make_float2((v1.x - u1.x * rc) * v1.x,
                                                       (v1.y - u1.y * rc) * v1.y));
            __half2 h3 = __float22half2_rn(make_float2((v1.z - u1.z * rc) * v1.z,
                                                       (v1.w - u1.w * rc) * v1.w));
            uint32_t q0 = *(uint32_t*)&h0, q1 = *(uint32_t*)&h1;
            uint32_t q2 = *(uint32_t*)&h2, q3 = *(uint32_t*)&h3;
            asm volatile("st.shared.v4.b32 [%0], {%1,%2,%3,%4};"
                         :: "r"(dst), "r"(q0), "r"(q1), "r"(q2), "r"(q3));
        } else {
            STS_ZERO(dst);
        }
    }
    CP_WAIT(0);
    __syncthreads();

    const int wm = (wid >> 1) * 32;
    const int wn = (wid & 1) * 32;
    float acc[2][4][4] = {};
    mma_tile_64(a_s, w_s, lane, wm, wn, acc);

    const int qr = lane >> 2, qc = lane & 3;
#pragma unroll
    for (int mt = 0; mt < 2; mt++)
#pragma unroll
        for (int nt = 0; nt < 4; nt++) {
            int col = wn + nt * 8 + qc * 2;
            float2 bv = *(const float2*)&pb[si * 64 + col];
            float2 sv = *(const float2*)&ps[si * 64 + col];
            float2 b2 = *(const float2*)&pbb[si * 64 + col];
            int r0 = m0 + wm + mt * 16 + qr;
            int r1 = r0 + 8;
            if (r0 < MP) *(float2*)&msO[(size_t)r0 * 64 + col] = make_float2(
                lrelu((acc[mt][nt][0] + bv.x) * sv.x + b2.x, 0.01f),
                lrelu((acc[mt][nt][1] + bv.y) * sv.y + b2.y, 0.01f));
            if (r1 < MP) *(float2*)&msO[(size_t)r1 * 64 + col] = make_float2(
                lrelu((acc[mt][nt][2] + bv.x) * sv.x + b2.x, 0.01f),
                lrelu((acc[mt][nt][3] + bv.y) * sv.y + b2.y, 0.01f));
        }
}

// ===== tensorized attn: sumx built in-kernel (fp16), 4 GEMMs, fused output ====
__global__ __launch_bounds__(256) void attn_mma_kernel(
    const float* __restrict__ ms, const __half* __restrict__ Wa,
    const float* __restrict__ ab, const float* __restrict__ as_,
    const float* __restrict__ abb, float* __restrict__ fused) {
    __shared__ __align__(16) char smA[16384];
    __shared__ __align__(16) char smW[8192];
    const uint32_t a_s = smem_u32(smA);
    const uint32_t w_s = smem_u32(smW);
    const int tid = threadIdx.x;
    const int lane = tid & 31, wid = tid >> 5;
    const int m0 = blockIdx.x * 128;

#pragma unroll
    for (int j = 0; j < 4; j++) {
        int f = tid + j * 256;
        int r = f >> 3, c = f & 7;
        uint32_t dst = a_s + r * 128 + ((c ^ (r & 7)) << 4);
        int m = m0 + r;
        if (m < MP) {
            float sx[8] = {};
#pragma unroll
            for (int i = 0; i < 4; i++) {
                float4 v0 = *(const float4*)&ms[((size_t)i * MP + m) * 64 + c * 8];
                float4 v1 = *(const float4*)&ms[((size_t)i * MP + m) * 64 + c * 8 + 4];
                sx[0] += v0.x; sx[1] += v0.y; sx[2] += v0.z; sx[3] += v0.w;
                sx[4] += v1.x; sx[5] += v1.y; sx[6] += v1.z; sx[7] += v1.w;
            }
            __half2 h0 = __float22half2_rn(make_float2(sx[0], sx[1]));
            __half2 h1 = __float22half2_rn(make_float2(sx[2], sx[3]));
            __half2 h2 = __float22half2_rn(make_float2(sx[4], sx[5]));
            __half2 h3 = __float22half2_rn(make_float2(sx[6], sx[7]));
            uint32_t q0 = *(uint32_t*)&h0, q1 = *(uint32_t*)&h1;
            uint32_t q2 = *(uint32_t*)&h2, q3 = *(uint32_t*)&h3;
            asm volatile("st.shared.v4.b32 [%0], {%1,%2,%3,%4};"
                         :: "r"(dst), "r"(q0), "r"(q1), "r"(q2), "r"(q3));
        } else {
            STS_ZERO(dst);
        }
    }

    const int wm = (wid >> 1) * 32;
    const int wn = (wid & 1) * 32;
    const int qr = lane >> 2, qc = lane & 3;
    float fac[2][4][4] = {};

    for (int i = 0; i < 4; i++) {
        __syncthreads();
#pragma unroll
        for (int j = 0; j < 2; j++) {
            int f = tid + j * 256;
            int r = f >> 3, c = f & 7;
            CP16(w_s + r * 128 + ((c ^ (r & 7)) << 4),
                 Wa + (size_t)i * 4096 + r * 64 + c * 8);
        }
        CP_COMMIT();
        CP_WAIT(0);
        __syncthreads();

        float acc[2][4][4] = {};
        mma_tile_64(a_s, w_s, lane, wm, wn, acc);

#pragma unroll
        for (int mt = 0; mt < 2; mt++)
#pragma unroll
            for (int nt = 0; nt < 4; nt++) {
                int col = wn + nt * 8 + qc * 2;
                float2 bv = *(const float2*)&ab[i * 64 + col];
                float2 sv = *(const float2*)&as_[i * 64 + col];
                float2 b2 = *(const float2*)&abb[i * 64 + col];
                int r0 = m0 + wm + mt * 16 + qr;
                int r1 = r0 + 8;
                if (r0 < MP) {
                    float2 mv = *(const float2*)&ms[((size_t)i * MP + r0) * 64 + col];
                    float a0 = 1.0f / (1.0f + __expf(-((acc[mt][nt][0] + bv.x) * sv.x + b2.x)));
                    float a1 = 1.0f / (1.0f + __expf(-((acc[mt][nt][1] + bv.y) * sv.y + b2.y)));
                    fac[mt][nt][0] += a0 * mv.x;
                    fac[mt][nt][1] += a1 * mv.y;
                }
                if (r1 < MP) {
                    float2 mv = *(const float2*)&ms[((size_t)i * MP + r1) * 64 + col];
                    float a2 = 1.0f / (1.0f + __expf(-((acc[mt][nt][2] + bv.x) * sv.x + b2.x)));
                    float a3 = 1.0f / (1.0f + __expf(-((acc[mt][nt][3] + bv.y) * sv.y + b2.y)));
                    fac[mt][nt][2] += a2 * mv.x;
                    fac[mt][nt][3] += a3 * mv.y;
                }
            }
    }

#pragma unroll
    for (int mt = 0; mt < 2; mt++)
#pragma unroll
        for (int nt = 0; nt < 4; nt++) {
            int col = wn + nt * 8 + qc * 2;
            int r0 = m0 + wm + mt * 16 + qr;
            int r1 = r0 + 8;
            if (r0 < MP) *(float2*)&fused[(size_t)r0 * 64 + col] =
                make_float2(fac[mt][nt][0], fac[mt][nt][1]);
            if (r1 < MP) *(float2*)&fused[(size_t)r1 * 64 + col] =
                make_float2(fac[mt][nt][2], fac[mt][nt][3]);
        }
}

// ================================ N=20 heads ==================================
__global__ __launch_bounds__(256) void gemm_n20_kernel(
    const float* __restrict__ X, const float* __restrict__ W,
    const float* __restrict__ b, float* __restrict__ out) {
    __shared__ float Xs[128 * 68];
    __shared__ float Ws[64 * 20];
    __shared__ float bs[20];
    const int tid = threadIdx.x;
    const int m0 = blockIdx.x * 128;
#pragma unroll
    for (int j = 0; j < 8; j++) {
        int f = tid + 256 * j;
        int r = f >> 4, c4 = f & 15;
        int m = m0 + r;
        float4 v = make_float4(0.f, 0.f, 0.f, 0.f);
        if (m < MP) v = *(const float4*)&X[(size_t)m * 64 + c4 * 4];
        *(float4*)&Xs[r * 68 + c4 * 4] = v;
    }
    for (int f = tid; f < 64 * 20; f += 256) Ws[f] = W[f];
    if (tid < 20) bs[tid] = b[tid];
    __syncthreads();
    int r = tid >> 1, half = tid & 1, n0 = half * 10;
    int m = m0 + r;
    if (m < MP) {
        float acc[10];
#pragma unroll
        for (int j = 0; j < 10; j++) acc[j] = bs[n0 + j];
#pragma unroll 8
        for (int c = 0; c < 64; c++) {
            float x = Xs[r * 68 + c];
#pragma unroll
            for (int j = 0; j < 10; j++) acc[j] += x * Ws[c * 20 + n0 + j];
        }
#pragma unroll
        for (int j = 0; j < 10; j++) out[(size_t)m * 20 + n0 + j] = acc[j];
    }
}

// ==============================================================================
extern "C" void kernel_launch(void* const* d_in, const int* in_sizes, int n_in,
                              void* d_out, int out_size) {
    const float* feats   = (const float*)d_in[0];
    const float* w1a     = (const float*)d_in[1];
    const float* s1a     = (const float*)d_in[2];
    const float* b1a     = (const float*)d_in[3];
    const float* w3      = (const float*)d_in[4];
    const float* s3      = (const float*)d_in[5];
    const float* b3      = (const float*)d_in[6];
    const float* w1b     = (const float*)d_in[7];
    const float* s1b     = (const float*)d_in[8];
    const float* b1b     = (const float*)d_in[9];
    const float* aux_w   = (const float*)d_in[10];
    const float* aux_b   = (const float*)d_in[11];
    const float* proj_w  = (const float*)d_in[12];
    const float* proj_b  = (const float*)d_in[13];
    const float* proj_s  = (const float*)d_in[14];
    const float* proj_bb = (const float*)d_in[15];
    const float* attn_w  = (const float*)d_in[16];
    const float* attn_b  = (const float*)d_in[17];
    const float* attn_s  = (const float*)d_in[18];
    const float* attn_bb = (const float*)d_in[19];
    const float* head_w  = (const float*)d_in[20];
    const float* head_b  = (const float*)d_in[21];
    const int*   nbr     = (const int*)d_in[22];
    const int*   inv     = (const int*)d_in[23];

    float* out    = (float*)d_out;
    float* fused  = out;
    float* logits = out + (size_t)MP * 64;
    float* aux    = out + (size_t)MP * 84;

    float *pV, *pms, *pvs, *pvc;
    __half *pH16, *pB16, *pW1a, *pW1b, *pWp, *pWa;
    uint4 *pWf;
    cudaGetSymbolAddress((void**)&pV, g_V);
    cudaGetSymbolAddress((void**)&pms, g_ms);
    cudaGetSymbolAddress((void**)&pvs, g_vsum4);
    cudaGetSymbolAddress((void**)&pvc, g_vcnt4);
    cudaGetSymbolAddress((void**)&pH16, g_H16);
    cudaGetSymbolAddress((void**)&pB16, g_B16);
    cudaGetSymbolAddress((void**)&pW1a, g_W1a16);
    cudaGetSymbolAddress((void**)&pW1b, g_W1b16);
    cudaGetSymbolAddress((void**)&pWp, g_Wp16);
    cudaGetSymbolAddress((void**)&pWa, g_Wa16);
    cudaGetSymbolAddress((void**)&pWf, g_Wf);

    cudaFuncSetAttribute(conv27_mma_kernel, cudaFuncAttributeMaxDynamicSharedMemorySize, CV_TOT);

    wprep_kernel<<<(16 * 4096 + 255) / 256, 256>>>(w1a, w1b, proj_w, attn_w,
                                                   pW1a, pW1b, pWp, pWa);
    wfrag_kernel<<<216, 256>>>(w3, pWf);

    gemm64hf_kernel<<<GTC, 256>>>(feats, pW1a, s1a, b1a, pH16);
    for (int i = 0; i < 4; i++) {
        conv27_mma_kernel<<<GTC, 256, CV_TOT>>>(pH16, nbr, pWf + (size_t)i * 27 * 512,
                                                s3 + i * 64, b3 + i * 64, pB16);
        if (i < 3) {
            gemm64h2_kernel<<<GTC, 256>>>(pB16,
                                          pW1b + (size_t)i * 4096, s1b + i * 64, b1b + i * 64,
                                          pW1a + (size_t)(i + 1) * 4096, s1a + (i + 1) * 64,
                                          b1a + (i + 1) * 64, pH16);
        } else {
            gemm64h_res_kernel<<<GTC, 256>>>(pB16, pW1b + (size_t)i * 4096, s1b + i * 64,
                                             b1b + i * 64, pV, feats);
        }
    }

    gemm_n20_kernel<<<938, 256>>>(pV, aux_w, aux_b, aux);

    zero_all_kernel<<<30000, 256>>>(pvs, pvc);
    scatter_all_kernel<<<120000, 256>>>(pV, inv, pvs, pvc);
    {
        dim3 grid(GTC, 4);
        proj_mma_kernel<<<grid, 256>>>(pV, inv, pvs, pvc, pWp,
                                       proj_b, proj_s, proj_bb, pms);
    }
    attn_mma_kernel<<<GTC, 256>>>(pms, pWa, attn_b, attn_s, attn_bb, fused);
    gemm_n20_kernel<<<938, 256>>>(fused, head_w, head_b, logits);
}